// round 5
// baseline (speedup 1.0000x reference)
#include <cuda_runtime.h>
#include <cuda_bf16.h>
#include <stdint.h>

// AuxSpatialGatherModule: out[b,c,k] = mean_{n: label[b,n]==k} feats[b,c,n]
// B=16, C=512, HW=16384, K=19 (class 19 = ignore/overflow dump slot).
//
//   k0: detect whether gt buffer is int64 or int32
//   k1: per-b: pack labels to uint8 (4/word) + per-class counts -> 1/count
//   k2: per-(b,c): stream 16384 floats, lane-replicated smem accumulators
//       acc[warp][class][lane] (bank==lane -> conflict free, no atomics).
//       Labels read via LDG (L2-resident, 16KB/batch shared by 512 blocks).
//       Front-batched 2x float4 loads per iteration for MLP.

#define NUM_CLASSES 19
#define SLOTS       20            // 19 classes + dump slot for ignore/invalid
#define MAX_B       16
#define MAX_HW4     4096          // HW/4 = 16384/4

__device__ uint32_t g_labels_d[MAX_B * MAX_HW4];  // packed uint8 labels
__device__ float    g_inv_d[MAX_B * SLOTS];       // 1/count (0 if empty / dump)
__device__ int      g_is64_d;

// ---------------------------------------------------------------------------
// k0: dtype detection. If the gt buffer is int64, every odd 32-bit word is a
// high word == 0 (labels are tiny). Random int32 labels make that essentially
// impossible across 2048 samples.
__global__ void detect_dtype_kernel(const uint32_t* __restrict__ g, int n_elem)
{
    __shared__ int nz;
    if (threadIdx.x == 0) nz = 0;
    __syncthreads();
    int limit = n_elem / 2;           // safe to index 2*i+1 < n_elem (int32 case)
    if (limit > 2048) limit = 2048;
    int f = 0;
    for (int i = threadIdx.x; i < limit; i += blockDim.x)
        f |= (g[2 * i + 1] != 0u);
    if (f) nz = 1;                    // benign race
    __syncthreads();
    if (threadIdx.x == 0) g_is64_d = (nz == 0);
}

// ---------------------------------------------------------------------------
// k1: labels -> packed uint8 + per-class counts -> reciprocal.
// Lane-replicated integer histogram (no shared atomics).
__global__ __launch_bounds__(512) void prep_kernel(const uint32_t* __restrict__ gt32,
                                                   int HW4)
{
    __shared__ int   scnt[16 * SLOTS * 32];   // 16 warps x 20 classes x 32 lanes
    const int b    = blockIdx.x;
    const int tid  = threadIdx.x;
    const int warp = tid >> 5;
    const int lane = tid & 31;

    for (int i = tid; i < 16 * SLOTS * 32; i += 512) scnt[i] = 0;
    __syncthreads();

    const int is64 = g_is64_d;
    const uint32_t* base = gt32 + (size_t)b * (size_t)(HW4 * 4) * (is64 ? 2 : 1);
    int* mycnt = scnt + warp * (SLOTS * 32) + lane;

    for (int w = tid; w < HW4; w += 512) {
        uint32_t packed = 0;
#pragma unroll
        for (int j = 0; j < 4; j++) {
            int i  = w * 4 + j;
            int v  = (int)(is64 ? base[2 * i] : base[i]);  // low word if int64
            uint32_t cls;
            if (v == 255)      cls = 19u;                  // ignore_index
            else if (v < 0)    cls = 0u;                   // clip low
            else if (v > 18)   cls = 18u;                  // clip high
            else               cls = (uint32_t)v;
            mycnt[cls * 32] += 1;
            packed |= cls << (8 * j);
        }
        g_labels_d[b * HW4 + w] = packed;
    }
    __syncthreads();

    // reduce 16 warp replicas -> 640 columns
    for (int col = tid; col < SLOTS * 32; col += 512) {
        int s = 0;
#pragma unroll
        for (int ww = 0; ww < 16; ww++) s += scnt[ww * (SLOTS * 32) + col];
        scnt[col] = s;
    }
    __syncthreads();

    if (tid < SLOTS) {
        int s = 0;
#pragma unroll
        for (int l = 0; l < 32; l++) s += scnt[tid * 32 + l];
        g_inv_d[b * SLOTS + tid] = (tid < NUM_CLASSES && s > 0) ? 1.0f / (float)s : 0.0f;
    }
}

// ---------------------------------------------------------------------------
// k2: main streaming reduction. One block per (b,c) row.
__global__ __launch_bounds__(256) void gather_kernel(const float* __restrict__ feats,
                                                     float* __restrict__ out,
                                                     int C, int HW4)
{
    __shared__ float acc[8 * SLOTS * 32];      // 8 warps x 20 x 32 = 20480 B

    const int tid  = threadIdx.x;
    const int warp = tid >> 5;
    const int lane = tid & 31;
    const int bc   = blockIdx.x;               // b*C + c
    const int b    = bc / C;

    for (int i = tid; i < 8 * SLOTS * 32; i += 256) acc[i] = 0.0f;
    __syncthreads();

    const float4*   __restrict__ f4   = (const float4*)(feats + (size_t)bc * (size_t)(HW4 * 4));
    const uint32_t* __restrict__ labs = g_labels_d + b * HW4;
    float* myacc = acc + warp * (SLOTS * 32) + lane;

    // Main loop: 2 independent float4 loads batched up-front per iteration.
    int idx = tid;
#pragma unroll 4
    for (; idx + 256 < HW4; idx += 512) {
        float4   v0 = f4[idx];
        float4   v1 = f4[idx + 256];
        uint32_t l0 = __ldg(labs + idx);
        uint32_t l1 = __ldg(labs + idx + 256);

        myacc[((l0      ) & 255u) * 32] += v0.x;
        myacc[((l0 >>  8) & 255u) * 32] += v0.y;
        myacc[((l0 >> 16) & 255u) * 32] += v0.z;
        myacc[((l0 >> 24)        ) * 32] += v0.w;

        myacc[((l1      ) & 255u) * 32] += v1.x;
        myacc[((l1 >>  8) & 255u) * 32] += v1.y;
        myacc[((l1 >> 16) & 255u) * 32] += v1.z;
        myacc[((l1 >> 24)        ) * 32] += v1.w;
    }
    // Remainder (shape-generic; empty when HW4 % 512 == 0)
    for (; idx < HW4; idx += 256) {
        float4   v  = f4[idx];
        uint32_t lw = __ldg(labs + idx);
        myacc[((lw      ) & 255u) * 32] += v.x;
        myacc[((lw >>  8) & 255u) * 32] += v.y;
        myacc[((lw >> 16) & 255u) * 32] += v.z;
        myacc[((lw >> 24)        ) * 32] += v.w;
    }
    __syncthreads();

    // reduce 8 warp replicas -> 640 columns (disjoint per thread, no hazard)
    for (int col = tid; col < SLOTS * 32; col += 256) {
        float s = 0.0f;
#pragma unroll
        for (int w = 0; w < 8; w++) s += acc[w * (SLOTS * 32) + col];
        acc[col] = s;
    }
    __syncthreads();

    if (tid < NUM_CLASSES) {
        float s = 0.0f;
#pragma unroll
        for (int l = 0; l < 32; l++) s += acc[tid * 32 + l];
        out[(size_t)bc * NUM_CLASSES + tid] = s * g_inv_d[b * SLOTS + tid];
    }
}

// ---------------------------------------------------------------------------
extern "C" void kernel_launch(void* const* d_in, const int* in_sizes, int n_in,
                              void* d_out, int out_size)
{
    const float*    feats = (const float*)d_in[0];
    const uint32_t* gt32  = (const uint32_t*)d_in[1];
    float*          out   = (float*)d_out;

    const int total_f = in_sizes[0];            // B*C*HW
    const int total_g = in_sizes[1];            // B*HW
    const int C  = total_f / total_g;           // 512
    const int BC = out_size / NUM_CLASSES;      // B*C
    const int B  = BC / C;                      // 16
    const int HW = total_g / B;                 // 16384
    const int HW4 = HW / 4;

    detect_dtype_kernel<<<1, 256>>>(gt32, total_g);
    prep_kernel<<<B, 512>>>(gt32, HW4);
    gather_kernel<<<BC, 256>>>(feats, out, C, HW4);
}

// round 9
// speedup vs baseline: 1.0908x; 1.0908x over previous
#include <cuda_runtime.h>
#include <cuda_bf16.h>
#include <stdint.h>

// AuxSpatialGatherModule: out[b,c,k] = mean_{n: label[b,n]==k} feats[b,c,n]
// B=16, C=512, HW=16384, K=19 (class 19 = ignore/overflow dump slot).
//
//   k1: per-b: inline int64/int32 detection + pack labels to uint8 (4/word)
//       + per-class counts -> 1/count
//   k2: per-(b,c): stream 16384 floats, lane-replicated smem accumulators
//       acc[warp][class][lane] (bank==lane -> conflict free, no atomics).
//       Labels via LDG (L2-resident); feats via __ldcs (streaming, read-once).
//       Front-batched 4x float4 loads per iteration for MLP.

#define NUM_CLASSES 19
#define SLOTS       20            // 19 classes + dump slot for ignore/invalid
#define MAX_B       16
#define MAX_HW4     4096          // HW/4 = 16384/4

__device__ uint32_t g_labels_d[MAX_B * MAX_HW4];  // packed uint8 labels
__device__ float    g_inv_d[MAX_B * SLOTS];       // 1/count (0 if empty / dump)

// ---------------------------------------------------------------------------
// k1: inline dtype detection + labels -> packed uint8 + per-class counts.
// Detection: if gt is int64 (little-endian), every odd 32-bit word is a high
// word == 0. Check the first 2048 odd words of the whole buffer (first 4096
// words are in-bounds under both interpretations since HW >= 4096 elements).
// P(false positive on random int32 labels in [0,19)) = (1/19)^2048 ~ 0.
__global__ __launch_bounds__(512) void prep_kernel(const uint32_t* __restrict__ gt32,
                                                   int HW4)
{
    __shared__ int   scnt[16 * SLOTS * 32];   // 16 warps x 20 classes x 32 lanes
    __shared__ int   s_nz;
    const int b    = blockIdx.x;
    const int tid  = threadIdx.x;
    const int warp = tid >> 5;
    const int lane = tid & 31;

    if (tid == 0) s_nz = 0;
    for (int i = tid; i < 16 * SLOTS * 32; i += 512) scnt[i] = 0;
    __syncthreads();

    // dtype detection (all blocks scan the same leading region)
    {
        int f = 0;
        int limit = (HW4 * 2 < 2048) ? HW4 * 2 : 2048;   // odd-word count to test
        for (int i = tid; i < limit; i += 512)
            f |= (gt32[2 * i + 1] != 0u);
        if (f) s_nz = 1;                                  // benign race
    }
    __syncthreads();
    const int is64 = (s_nz == 0);

    const uint32_t* base = gt32 + (size_t)b * (size_t)(HW4 * 4) * (is64 ? 2 : 1);
    int* mycnt = scnt + warp * (SLOTS * 32) + lane;

    for (int w = tid; w < HW4; w += 512) {
        uint32_t packed = 0;
#pragma unroll
        for (int j = 0; j < 4; j++) {
            int i  = w * 4 + j;
            int v  = (int)(is64 ? base[2 * i] : base[i]);  // low word if int64
            uint32_t cls;
            if (v == 255)      cls = 19u;                  // ignore_index
            else if (v < 0)    cls = 0u;                   // clip low
            else if (v > 18)   cls = 18u;                  // clip high
            else               cls = (uint32_t)v;
            mycnt[cls * 32] += 1;
            packed |= cls << (8 * j);
        }
        g_labels_d[b * HW4 + w] = packed;
    }
    __syncthreads();

    // reduce 16 warp replicas -> 640 columns
    for (int col = tid; col < SLOTS * 32; col += 512) {
        int s = 0;
#pragma unroll
        for (int ww = 0; ww < 16; ww++) s += scnt[ww * (SLOTS * 32) + col];
        scnt[col] = s;
    }
    __syncthreads();

    if (tid < SLOTS) {
        int s = 0;
#pragma unroll
        for (int l = 0; l < 32; l++) s += scnt[tid * 32 + l];
        g_inv_d[b * SLOTS + tid] = (tid < NUM_CLASSES && s > 0) ? 1.0f / (float)s : 0.0f;
    }
}

// ---------------------------------------------------------------------------
// k2: main streaming reduction. One block per (b,c) row.
__global__ __launch_bounds__(256) void gather_kernel(const float* __restrict__ feats,
                                                     float* __restrict__ out,
                                                     int C, int HW4)
{
    __shared__ float acc[8 * SLOTS * 32];      // 8 warps x 20 x 32 = 20480 B

    const int tid  = threadIdx.x;
    const int warp = tid >> 5;
    const int lane = tid & 31;
    const int bc   = blockIdx.x;               // b*C + c
    const int b    = bc / C;

    for (int i = tid; i < 8 * SLOTS * 32; i += 256) acc[i] = 0.0f;
    __syncthreads();

    const float4*   __restrict__ f4   = (const float4*)(feats + (size_t)bc * (size_t)(HW4 * 4));
    const uint32_t* __restrict__ labs = g_labels_d + b * HW4;
    float* myacc = acc + warp * (SLOTS * 32) + lane;

    // Main loop: 4 independent float4 streaming loads batched up-front.
    int idx = tid;
#pragma unroll 2
    for (; idx + 768 < HW4; idx += 1024) {
        float4   v0 = __ldcs(f4 + idx);
        float4   v1 = __ldcs(f4 + idx + 256);
        float4   v2 = __ldcs(f4 + idx + 512);
        float4   v3 = __ldcs(f4 + idx + 768);
        uint32_t l0 = __ldg(labs + idx);
        uint32_t l1 = __ldg(labs + idx + 256);
        uint32_t l2 = __ldg(labs + idx + 512);
        uint32_t l3 = __ldg(labs + idx + 768);

        myacc[((l0      ) & 255u) * 32] += v0.x;
        myacc[((l0 >>  8) & 255u) * 32] += v0.y;
        myacc[((l0 >> 16) & 255u) * 32] += v0.z;
        myacc[((l0 >> 24)        ) * 32] += v0.w;

        myacc[((l1      ) & 255u) * 32] += v1.x;
        myacc[((l1 >>  8) & 255u) * 32] += v1.y;
        myacc[((l1 >> 16) & 255u) * 32] += v1.z;
        myacc[((l1 >> 24)        ) * 32] += v1.w;

        myacc[((l2      ) & 255u) * 32] += v2.x;
        myacc[((l2 >>  8) & 255u) * 32] += v2.y;
        myacc[((l2 >> 16) & 255u) * 32] += v2.z;
        myacc[((l2 >> 24)        ) * 32] += v2.w;

        myacc[((l3      ) & 255u) * 32] += v3.x;
        myacc[((l3 >>  8) & 255u) * 32] += v3.y;
        myacc[((l3 >> 16) & 255u) * 32] += v3.z;
        myacc[((l3 >> 24)        ) * 32] += v3.w;
    }
    // Remainder (shape-generic; empty when HW4 % 1024 == 0)
    for (; idx < HW4; idx += 256) {
        float4   v  = __ldcs(f4 + idx);
        uint32_t lw = __ldg(labs + idx);
        myacc[((lw      ) & 255u) * 32] += v.x;
        myacc[((lw >>  8) & 255u) * 32] += v.y;
        myacc[((lw >> 16) & 255u) * 32] += v.z;
        myacc[((lw >> 24)        ) * 32] += v.w;
    }
    __syncthreads();

    // reduce 8 warp replicas -> 640 columns (disjoint per thread, no hazard)
    for (int col = tid; col < SLOTS * 32; col += 256) {
        float s = 0.0f;
#pragma unroll
        for (int w = 0; w < 8; w++) s += acc[w * (SLOTS * 32) + col];
        acc[col] = s;
    }
    __syncthreads();

    if (tid < NUM_CLASSES) {
        float s = 0.0f;
#pragma unroll
        for (int l = 0; l < 32; l++) s += acc[tid * 32 + l];
        out[(size_t)bc * NUM_CLASSES + tid] = s * g_inv_d[b * SLOTS + tid];
    }
}

// ---------------------------------------------------------------------------
extern "C" void kernel_launch(void* const* d_in, const int* in_sizes, int n_in,
                              void* d_out, int out_size)
{
    const float*    feats = (const float*)d_in[0];
    const uint32_t* gt32  = (const uint32_t*)d_in[1];
    float*          out   = (float*)d_out;

    const int total_f = in_sizes[0];            // B*C*HW
    const int total_g = in_sizes[1];            // B*HW
    const int C  = total_f / total_g;           // 512
    const int BC = out_size / NUM_CLASSES;      // B*C
    const int B  = BC / C;                      // 16
    const int HW = total_g / B;                 // 16384
    const int HW4 = HW / 4;

    prep_kernel<<<B, 512>>>(gt32, HW4);
    gather_kernel<<<BC, 256>>>(feats, out, C, HW4);
}